// round 11
// baseline (speedup 1.0000x reference)
#include <cuda_runtime.h>
#include <cstdint>

#define N_CELLS  8388608
#define N_HALO   1048576
#define NFIELDS  12
#define BSHIFT   11
#define NBUCKETS 4096           // N_CELLS >> BSHIFT
#define CPB      2048           // cells per bucket
#define SLAB     768            // record capacity per bucket (mean 366, +21 sd)
#define SMEM_SZ  (NFIELDS * CPB * 4)   // 98304 B
#define LOC_MASK (CPB - 1)
#define HALFBIT  0x800
#define K5_THR   512

__device__ int   g_cur[NBUCKETS];                      // per-bucket count
__device__ int   g_rec[NBUCKETS * SLAB];               // 12 MB
__device__ int2  g_pos[N_HALO];                        // 8 MB
__device__ float g_cscr[(size_t)NBUCKETS * SLAB * 12]; // 151 MB

// ---------------------------------------------------------------------------
__global__ void k0_zero() { g_cur[blockIdx.x * 1024 + threadIdx.x] = 0; }

// ---------------------------------------------------------------------------
// Fused pack + rank + reserve + scatter, ONE smem atomic per contribution.
// 256 blocks x 1024 threads x 4 elements.
__global__ __launch_bounds__(1024) void k_bin(
    const int2* __restrict__ src_idx, const float2* __restrict__ weights)
{
    __shared__ int sh_cnt[NBUCKETS];    // 16 KB: rank counter -> final count
    __shared__ int sh_base[NBUCKETS];   // 16 KB: reserved global base
    const int tid   = threadIdx.x;
    const int ebase = blockIdx.x * 4096;

    for (int j = tid; j < NBUCKETS; j += 1024) sh_cnt[j] = 0;
    __syncthreads();

    int  i0[4], i1[4], l0[4], l1[4];
    bool cc[4];
    #pragma unroll
    for (int k = 0; k < 4; k++) {
        const int e = ebase + k * 1024 + tid;
        const int2   i = __ldcs(src_idx + e);
        const float2 w = __ldcs(weights + e);
        cc[k] = (w.y != 0.0f);
        i0[k] = i.x;  i1[k] = i.y;
        l0[k] = atomicAdd(&sh_cnt[i.x >> BSHIFT], 1);      // local rank, pass 1
        l1[k] = cc[k] ? atomicAdd(&sh_cnt[i.y >> BSHIFT], 1) : 0;
    }
    __syncthreads();

    // Reserve a sub-slab per nonzero bin (spread-address global atomics).
    for (int j = tid; j < NBUCKETS; j += 1024) {
        const int c = sh_cnt[j];
        sh_base[j] = c ? atomicAdd(&g_cur[j], c) : 0;
    }
    __syncthreads();

    #pragma unroll
    for (int k = 0; k < 4; k++) {
        const int e  = ebase + k * 1024 + tid;
        const int b0 = i0[k] >> BSHIFT;
        const int s0 = b0 * SLAB + sh_base[b0] + l0[k];
        g_rec[s0] = (i0[k] & LOC_MASK) | (cc[k] ? HALFBIT : 0);
        int s1 = -1;
        if (cc[k]) {
            const int b1 = i1[k] >> BSHIFT;
            s1 = b1 * SLAB + sh_base[b1] + l1[k];
            g_rec[s1] = (i1[k] & LOC_MASK) | HALFBIT;
        }
        g_pos[e] = make_int2(s0, s1);
    }
}

// ---------------------------------------------------------------------------
// Stage 2048 cells x 12 fields in smem (coalesced), serve this bucket's
// contributions from LDS, write weighted 11-value records (48 B, coalesced).
// 512 threads/block, 2 CTA/SM -> 1024 threads/SM driving the staging loads.
__global__ __launch_bounds__(K5_THR) void k5_gather(const float* __restrict__ fields)
{
    extern __shared__ float sf[];
    const int b    = blockIdx.x;
    const int base = b << BSHIFT;

    float4* s4 = (float4*)sf;
    for (int i = threadIdx.x; i < NFIELDS * (CPB / 4); i += K5_THR) {
        const int f = i >> 9;       // / (CPB/4)
        const int j = i & 511;
        s4[i] = __ldcg((const float4*)(fields + (size_t)f * N_CELLS + base) + j);
    }
    __syncthreads();

    const int lo = b * SLAB;
    const int n  = g_cur[b];
    for (int t = threadIdx.x; t < n; t += K5_THR) {
        const int  rec = g_rec[lo + t];
        const int  l   = rec & LOC_MASK;
        const float w  = (rec & HALFBIT) ? 0.5f : 1.0f;

        const float u  = sf[ 0*CPB + l], v  = sf[ 1*CPB + l];
        const float bu = sf[ 2*CPB + l], bv = sf[ 3*CPB + l];
        const float h  = sf[ 4*CPB + l], Hb = sf[ 5*CPB + l];
        const float hh = sf[ 6*CPB + l], dh = sf[ 7*CPB + l];
        const float et = sf[ 8*CPB + l];
        const float ku = sf[ 9*CPB + l], kv = sf[10*CPB + l], k3 = sf[11*CPB + l];

        float4* dst = (float4*)&g_cscr[(size_t)(lo + t) * 12];
        dst[0] = make_float4(w * u,  w * v,  w * bu, w * bv);
        dst[1] = make_float4(w * h,  w * hh, w * dh, w * (h + Hb));
        dst[2] = make_float4(w * et, w * fminf(ku, k3), w * fminf(kv, k3), 0.0f);
    }
}

// ---------------------------------------------------------------------------
// Combine: per element sum its 1-2 records (fixed order r0 then r1), then
// coalesced row stores. Bit-deterministic across replays.
__global__ __launch_bounds__(256) void k6_combine(float* __restrict__ out)
{
    const int e = blockIdx.x * 256 + threadIdx.x;
    const int2 p = g_pos[e];
    const float4* r0 = (const float4*)&g_cscr[(size_t)p.x * 12];
    float4 A = __ldg(r0), B = __ldg(r0 + 1), C = __ldg(r0 + 2);
    if (p.y >= 0) {
        const float4* r1 = (const float4*)&g_cscr[(size_t)p.y * 12];
        const float4 A1 = __ldg(r1), B1 = __ldg(r1 + 1), C1 = __ldg(r1 + 2);
        A.x += A1.x; A.y += A1.y; A.z += A1.z; A.w += A1.w;
        B.x += B1.x; B.y += B1.y; B.z += B1.z; B.w += B1.w;
        C.x += C1.x; C.y += C1.y; C.z += C1.z;
    }
    out[ 0*N_HALO + e] = A.x; out[ 1*N_HALO + e] = A.y;
    out[ 2*N_HALO + e] = A.z; out[ 3*N_HALO + e] = A.w;
    out[ 4*N_HALO + e] = B.x; out[ 5*N_HALO + e] = B.y;
    out[ 6*N_HALO + e] = B.z; out[ 7*N_HALO + e] = B.w;
    out[ 8*N_HALO + e] = C.x; out[ 9*N_HALO + e] = C.y;
    out[10*N_HALO + e] = C.z;
}

extern "C" void kernel_launch(void* const* d_in, const int* in_sizes, int n_in,
                              void* d_out, int out_size)
{
    const float*  fields  = (const float*)d_in[0];
    const int2*   src_idx = (const int2*)d_in[1];
    const float2* weights = (const float2*)d_in[2];
    float*        out     = (float*)d_out;

    cudaFuncSetAttribute(k5_gather,
                         cudaFuncAttributeMaxDynamicSharedMemorySize, SMEM_SZ);

    k0_zero   <<<NBUCKETS / 1024, 1024>>>();
    k_bin     <<<256, 1024>>>(src_idx, weights);
    k5_gather <<<NBUCKETS, K5_THR, SMEM_SZ>>>(fields);
    k6_combine<<<N_HALO / 256, 256>>>(out);
}

// round 12
// speedup vs baseline: 1.0119x; 1.0119x over previous
#include <cuda_runtime.h>
#include <cstdint>

#define N_CELLS  8388608
#define N_HALO   1048576
#define NFIELDS  12
#define NQOUT    11
#define BSHIFT   11
#define NBUCKETS 4096           // N_CELLS >> BSHIFT
#define CPB      2048           // cells per bucket
#define SLAB     768            // record capacity per bucket (mean 366, +21 sd)
#define SMEM_SZ  (NFIELDS * CPB * 4)   // 98304 B
#define LOC_MASK (CPB - 1)

__device__ int      g_cur[NBUCKETS];            // per-bucket count
__device__ unsigned g_rec[NBUCKETS * SLAB];     // 12 MB: e<<12 | loc<<1 | half

// ---------------------------------------------------------------------------
// Zero out (46 MB, float4) and g_cur. Grid exactly covers out4.
__global__ __launch_bounds__(256) void k_zero(float4* __restrict__ out4)
{
    const int t = blockIdx.x * 256 + threadIdx.x;
    if (t < NBUCKETS) g_cur[t] = 0;
    out4[t] = make_float4(0.f, 0.f, 0.f, 0.f);
}

// ---------------------------------------------------------------------------
// Fused pack + histogram + reserve + scatter (R10-proven two-pass shape).
// 256 blocks x 1024 threads x 4 elements. Records carry e, so no g_pos.
__global__ __launch_bounds__(1024) void k_bin(
    const int2* __restrict__ src_idx, const float2* __restrict__ weights)
{
    __shared__ int sh_cnt[NBUCKETS];    // 16 KB
    __shared__ int sh_base[NBUCKETS];   // 16 KB
    const int tid   = threadIdx.x;
    const int ebase = blockIdx.x * 4096;

    for (int j = tid; j < NBUCKETS; j += 1024) sh_cnt[j] = 0;
    __syncthreads();

    int  i0[4], i1[4];
    bool cc[4];
    #pragma unroll
    for (int k = 0; k < 4; k++) {
        const int e = ebase + k * 1024 + tid;
        const int2   i = __ldcs(src_idx + e);
        const float2 w = __ldcs(weights + e);
        cc[k] = (w.y != 0.0f);
        i0[k] = i.x;  i1[k] = i.y;
        atomicAdd(&sh_cnt[i.x >> BSHIFT], 1);        // no result -> RED.shared
        if (cc[k]) atomicAdd(&sh_cnt[i.y >> BSHIFT], 1);
    }
    __syncthreads();

    for (int j = tid; j < NBUCKETS; j += 1024) {
        const int c = sh_cnt[j];
        sh_base[j] = c ? atomicAdd(&g_cur[j], c) : 0;  // reserve sub-slab
        sh_cnt[j]  = 0;                                // reuse as rank counter
    }
    __syncthreads();

    #pragma unroll
    for (int k = 0; k < 4; k++) {
        const unsigned e = (unsigned)(ebase + k * 1024 + tid);
        const int b0 = i0[k] >> BSHIFT;
        const int s0 = b0 * SLAB + sh_base[b0] + atomicAdd(&sh_cnt[b0], 1);
        g_rec[s0] = (e << 12) | (unsigned)((i0[k] & LOC_MASK) << 1)
                  | (cc[k] ? 1u : 0u);
        if (cc[k]) {
            const int b1 = i1[k] >> BSHIFT;
            const int s1 = b1 * SLAB + sh_base[b1] + atomicAdd(&sh_cnt[b1], 1);
            g_rec[s1] = (e << 12) | (unsigned)((i1[k] & LOC_MASK) << 1) | 1u;
        }
    }
}

// ---------------------------------------------------------------------------
// Stage 2048 cells x 12 fields in smem (coalesced, evict-first), then serve
// this bucket's contributions from LDS and RED.ADD the 11 weighted derived
// values directly into out. fp32 add is commutative bitwise and each element
// receives <=2 contributions onto 0 -> replay-deterministic, exact.
__global__ __launch_bounds__(256) void k5_gather(
    const float* __restrict__ fields, float* __restrict__ out)
{
    extern __shared__ float sf[];
    const int b    = blockIdx.x;
    const int base = b << BSHIFT;

    float4* s4 = (float4*)sf;
    for (int i = threadIdx.x; i < NFIELDS * (CPB / 4); i += 256) {
        const int f = i >> 9;       // / (CPB/4)
        const int j = i & 511;
        s4[i] = __ldcs((const float4*)(fields + (size_t)f * N_CELLS + base) + j);
    }
    __syncthreads();

    const int lo = b * SLAB;
    const int n  = g_cur[b];
    for (int t = threadIdx.x; t < n; t += 256) {
        const unsigned rec = g_rec[lo + t];
        const int   l = (int)((rec >> 1) & LOC_MASK);
        const float w = (rec & 1u) ? 0.5f : 1.0f;
        const unsigned e = rec >> 12;

        const float u  = sf[ 0*CPB + l], v  = sf[ 1*CPB + l];
        const float bu = sf[ 2*CPB + l], bv = sf[ 3*CPB + l];
        const float h  = sf[ 4*CPB + l], Hb = sf[ 5*CPB + l];
        const float hh = sf[ 6*CPB + l], dh = sf[ 7*CPB + l];
        const float et = sf[ 8*CPB + l];
        const float ku = sf[ 9*CPB + l], kv = sf[10*CPB + l], k3 = sf[11*CPB + l];

        float* o = out + e;
        atomicAdd(o + 0u * N_HALO, w * u);
        atomicAdd(o + 1u * N_HALO, w * v);
        atomicAdd(o + 2u * N_HALO, w * bu);
        atomicAdd(o + 3u * N_HALO, w * bv);
        atomicAdd(o + 4u * N_HALO, w * h);
        atomicAdd(o + 5u * N_HALO, w * hh);
        atomicAdd(o + 6u * N_HALO, w * dh);
        atomicAdd(o + 7u * N_HALO, w * (h + Hb));
        atomicAdd(o + 8u * N_HALO, w * et);
        atomicAdd(o + 9u * N_HALO, w * fminf(ku, k3));
        atomicAdd(o + 10u * N_HALO, w * fminf(kv, k3));
    }
}

extern "C" void kernel_launch(void* const* d_in, const int* in_sizes, int n_in,
                              void* d_out, int out_size)
{
    const float*  fields  = (const float*)d_in[0];
    const int2*   src_idx = (const int2*)d_in[1];
    const float2* weights = (const float2*)d_in[2];
    float*        out     = (float*)d_out;

    cudaFuncSetAttribute(k5_gather,
                         cudaFuncAttributeMaxDynamicSharedMemorySize, SMEM_SZ);

    const int out4 = (NQOUT * N_HALO) / 4;            // 2883584 float4s
    k_zero   <<<out4 / 256, 256>>>((float4*)out);
    k_bin    <<<256, 1024>>>(src_idx, weights);
    k5_gather<<<NBUCKETS, 256, SMEM_SZ>>>(fields, out);
}

// round 13
// speedup vs baseline: 1.3905x; 1.3741x over previous
#include <cuda_runtime.h>
#include <cstdint>

#define N_CELLS  8388608
#define N_HALO   1048576
#define NFIELDS  12
#define BSHIFT   10
#define NBUCKETS 8192           // N_CELLS >> BSHIFT
#define CPB      1024           // cells per bucket
#define SLAB     384            // record cap per bucket (mean 183, +15 sd)
#define LOC_MASK (CPB - 1)
#define HALFBIT  0x800
#define BUF_FL   (NFIELDS * CPB)            // floats per buffer (48 KB)
#define K5_SMEM  (2 * BUF_FL * 4)           // 98304 B
#define KBIN_SMEM (2 * NBUCKETS * 4)        // 65536 B
#define NCTA     304                        // persistent k5 CTAs (2/SM)

__device__ int   g_cur[NBUCKETS];                      // per-bucket count
__device__ int   g_rec[NBUCKETS * SLAB];               // 12.6 MB
__device__ int2  g_pos[N_HALO];                        // 8 MB
__device__ float g_cscr[(size_t)NBUCKETS * SLAB * 12]; // 151 MB

// ---------------------------------------------------------------------------
__global__ void k0_zero() { g_cur[blockIdx.x * 1024 + threadIdx.x] = 0; }

// ---------------------------------------------------------------------------
// Fused pack + histogram + reserve + scatter (R10-proven two-pass shape).
// 256 blocks x 1024 threads x 4 elements. 64 KB dynamic smem (2 x 8192 ints).
__global__ __launch_bounds__(1024) void k_bin(
    const int2* __restrict__ src_idx, const float2* __restrict__ weights)
{
    extern __shared__ int sh[];
    int* sh_cnt  = sh;               // histogram -> rank counter
    int* sh_base = sh + NBUCKETS;    // reserved global base
    const int tid   = threadIdx.x;
    const int ebase = blockIdx.x * 4096;

    for (int j = tid; j < NBUCKETS; j += 1024) sh_cnt[j] = 0;
    __syncthreads();

    int  i0[4], i1[4];
    bool cc[4];
    #pragma unroll
    for (int k = 0; k < 4; k++) {
        const int e = ebase + k * 1024 + tid;
        const int2   i = __ldcs(src_idx + e);
        const float2 w = __ldcs(weights + e);
        cc[k] = (w.y != 0.0f);
        i0[k] = i.x;  i1[k] = i.y;
        atomicAdd(&sh_cnt[i.x >> BSHIFT], 1);          // result-free RED.shared
        if (cc[k]) atomicAdd(&sh_cnt[i.y >> BSHIFT], 1);
    }
    __syncthreads();

    for (int j = tid; j < NBUCKETS; j += 1024) {
        const int c = sh_cnt[j];
        sh_base[j] = c ? atomicAdd(&g_cur[j], c) : 0;  // spread global reserve
        sh_cnt[j]  = 0;                                // reuse as rank counter
    }
    __syncthreads();

    #pragma unroll
    for (int k = 0; k < 4; k++) {
        const int e  = ebase + k * 1024 + tid;
        const int b0 = i0[k] >> BSHIFT;
        const int s0 = b0 * SLAB + sh_base[b0] + atomicAdd(&sh_cnt[b0], 1);
        g_rec[s0] = (i0[k] & LOC_MASK) | (cc[k] ? HALFBIT : 0);
        int s1 = -1;
        if (cc[k]) {
            const int b1 = i1[k] >> BSHIFT;
            s1 = b1 * SLAB + sh_base[b1] + atomicAdd(&sh_cnt[b1], 1);
            g_rec[s1] = (i1[k] & LOC_MASK) | HALFBIT;
        }
        g_pos[e] = make_int2(s0, s1);
    }
}

// ---------------------------------------------------------------------------
// Persistent double-buffered gather: cp.async-stage bucket k+1's 12 field
// slices (48 KB) while serving bucket k from smem. Serve emits weighted
// 11-value records (48 B, coalesced) into g_cscr.
__global__ __launch_bounds__(256) void k5_gather(const float* __restrict__ fields)
{
    extern __shared__ float sf[];                 // 2 x BUF_FL
    const int c0 = (int)(((long long)blockIdx.x     * NBUCKETS) / NCTA);
    const int c1 = (int)(((long long)(blockIdx.x+1) * NBUCKETS) / NCTA);
    if (c0 >= c1) return;

    auto stage = [&](int buf, int b) {
        float* dst = sf + buf * BUF_FL;
        const int base = b << BSHIFT;
        for (int i = threadIdx.x; i < NFIELDS * (CPB / 4); i += 256) {
            const int f = i >> 8;                 // / (CPB/4)=256
            const int j = (i & 255) * 4;
            const float* src = fields + (size_t)f * N_CELLS + base + j;
            unsigned saddr = (unsigned)__cvta_generic_to_shared(dst + f * CPB + j);
            asm volatile("cp.async.cg.shared.global [%0], [%1], 16;\n"
                         :: "r"(saddr), "l"(src));
        }
        asm volatile("cp.async.commit_group;\n" ::: "memory");
    };

    stage(0, c0);
    for (int k = c0; k < c1; k++) {
        const int buf = (k - c0) & 1;
        if (k + 1 < c1) stage(buf ^ 1, k + 1);
        else asm volatile("cp.async.commit_group;\n" ::: "memory");
        asm volatile("cp.async.wait_group 1;\n" ::: "memory");  // buf k ready
        __syncthreads();

        const float* s = sf + buf * BUF_FL;
        const int lo = k * SLAB;
        const int n  = g_cur[k];
        for (int t = threadIdx.x; t < n; t += 256) {
            const int  rec = g_rec[lo + t];
            const int  l   = rec & LOC_MASK;
            const float w  = (rec & HALFBIT) ? 0.5f : 1.0f;

            const float u  = s[ 0*CPB + l], v  = s[ 1*CPB + l];
            const float bu = s[ 2*CPB + l], bv = s[ 3*CPB + l];
            const float h  = s[ 4*CPB + l], Hb = s[ 5*CPB + l];
            const float hh = s[ 6*CPB + l], dh = s[ 7*CPB + l];
            const float et = s[ 8*CPB + l];
            const float ku = s[ 9*CPB + l], kv = s[10*CPB + l], k3 = s[11*CPB + l];

            float4* dst = (float4*)&g_cscr[(size_t)(lo + t) * 12];
            dst[0] = make_float4(w * u,  w * v,  w * bu, w * bv);
            dst[1] = make_float4(w * h,  w * hh, w * dh, w * (h + Hb));
            dst[2] = make_float4(w * et, w * fminf(ku, k3), w * fminf(kv, k3), 0.0f);
        }
        __syncthreads();   // done reading buf before it is restaged next iter
    }
}

// ---------------------------------------------------------------------------
// Combine: per element sum its 1-2 records (fixed order r0 then r1), then
// coalesced row stores. Bit-deterministic across replays.
__global__ __launch_bounds__(256) void k6_combine(float* __restrict__ out)
{
    const int e = blockIdx.x * 256 + threadIdx.x;
    const int2 p = g_pos[e];
    const float4* r0 = (const float4*)&g_cscr[(size_t)p.x * 12];
    float4 A = __ldg(r0), B = __ldg(r0 + 1), C = __ldg(r0 + 2);
    if (p.y >= 0) {
        const float4* r1 = (const float4*)&g_cscr[(size_t)p.y * 12];
        const float4 A1 = __ldg(r1), B1 = __ldg(r1 + 1), C1 = __ldg(r1 + 2);
        A.x += A1.x; A.y += A1.y; A.z += A1.z; A.w += A1.w;
        B.x += B1.x; B.y += B1.y; B.z += B1.z; B.w += B1.w;
        C.x += C1.x; C.y += C1.y; C.z += C1.z;
    }
    out[ 0*N_HALO + e] = A.x; out[ 1*N_HALO + e] = A.y;
    out[ 2*N_HALO + e] = A.z; out[ 3*N_HALO + e] = A.w;
    out[ 4*N_HALO + e] = B.x; out[ 5*N_HALO + e] = B.y;
    out[ 6*N_HALO + e] = B.z; out[ 7*N_HALO + e] = B.w;
    out[ 8*N_HALO + e] = C.x; out[ 9*N_HALO + e] = C.y;
    out[10*N_HALO + e] = C.z;
}

extern "C" void kernel_launch(void* const* d_in, const int* in_sizes, int n_in,
                              void* d_out, int out_size)
{
    const float*  fields  = (const float*)d_in[0];
    const int2*   src_idx = (const int2*)d_in[1];
    const float2* weights = (const float2*)d_in[2];
    float*        out     = (float*)d_out;

    cudaFuncSetAttribute(k_bin,
                         cudaFuncAttributeMaxDynamicSharedMemorySize, KBIN_SMEM);
    cudaFuncSetAttribute(k5_gather,
                         cudaFuncAttributeMaxDynamicSharedMemorySize, K5_SMEM);

    k0_zero   <<<NBUCKETS / 1024, 1024>>>();
    k_bin     <<<256, 1024, KBIN_SMEM>>>(src_idx, weights);
    k5_gather <<<NCTA, 256, K5_SMEM>>>(fields);
    k6_combine<<<N_HALO / 256, 256>>>(out);
}